// round 2
// baseline (speedup 1.0000x reference)
#include <cuda_runtime.h>
#include <cuda_bf16.h>
#include <cstdint>

// ---------------------------------------------------------------------------
// Problem constants (shapes are fixed by the dataset)
// ---------------------------------------------------------------------------
#define BATCH   4
#define HH      128
#define WW_     256
#define L_TOK   (HH * WW_)          // 32768
#define CDIM    192
#define HEADS   6
#define HDIM    32                  // CDIM / HEADS
#define HIDDEN  768                 // 4 * CDIM
#define WINH    8
#define WINW    8
#define NWIN_Y  (HH / WINH)         // 16
#define NWIN_X  (WW_ / WINW)        // 32
#define NW      (NWIN_Y * NWIN_X)   // 512 windows per batch image
#define BWIN    (BATCH * NW)        // 2048 total windows
#define NTOK    (WINH * WINW)       // 64 tokens per window
#define MROWS   (BWIN * NTOK)       // 131072 total window tokens
#define SHIFT   4

// ---------------------------------------------------------------------------
// Scratch buffers (static device arrays: allocation-free)
// ---------------------------------------------------------------------------
__device__ float g_xw  [(size_t)MROWS * CDIM];    // LN1(x)  window layout
__device__ float g_x1w [(size_t)MROWS * CDIM];    // LN1(x1) window layout
__device__ float g_q   [(size_t)MROWS * CDIM];    // q
__device__ float g_kv  [(size_t)MROWS * 2 * CDIM];// kv (k cols 0..191, v cols 192..383)
__device__ float g_ao  [(size_t)MROWS * CDIM];    // attention output (window layout)
__device__ float g_xo  [(size_t)MROWS * CDIM];    // x + attn branch (image layout)
__device__ float g_xn2 [(size_t)MROWS * CDIM];    // LN2(xo)
__device__ float g_h   [(size_t)MROWS * HIDDEN];  // gelu(fc1)

// ---------------------------------------------------------------------------
// window row <-> image row map (shift roll folded in; padding is a no-op)
// ---------------------------------------------------------------------------
__device__ __forceinline__ int win_src_row(int r)
{
    int b_  = r >> 6;          // window id global
    int t   = r & 63;          // token within window
    int b   = b_ >> 9;         // batch  (nW = 512 = 2^9)
    int wid = b_ & 511;
    int wy  = wid >> 5;        // 32 windows per row  (W/8)
    int wx  = wid & 31;
    int i   = t >> 3;
    int j   = t & 7;
    int h   = (wy * 8 + i + SHIFT) & (HH - 1);
    int w   = (wx * 8 + j + SHIFT) & (WW_ - 1);
    return (b << 15) + (h << 8) + w;   // b*32768 + h*256 + w
}

__device__ __forceinline__ float warp_sum(float v)
{
#pragma unroll
    for (int o = 16; o > 0; o >>= 1) v += __shfl_xor_sync(0xffffffffu, v, o);
    return v;
}

__device__ __forceinline__ float gelu_exact(float v)
{
    return 0.5f * v * (1.0f + erff(v * 0.70710678118654752f));
}

// ---------------------------------------------------------------------------
// Kernel 1: LN(x), LN(x1) with gather into window layout.  192 thr / token.
// ---------------------------------------------------------------------------
__global__ void ln1_gather_kernel(const float* __restrict__ x,
                                  const float* __restrict__ x1,
                                  const float* __restrict__ g,
                                  const float* __restrict__ bb,
                                  float* __restrict__ xw,
                                  float* __restrict__ x1w)
{
    int r   = blockIdx.x;
    int src = win_src_row(r);
    int t   = threadIdx.x;

    float v0 = x [(size_t)src * CDIM + t];
    float v1 = x1[(size_t)src * CDIM + t];

    float s0 = warp_sum(v0), q0 = warp_sum(v0 * v0);
    float s1 = warp_sum(v1), q1 = warp_sum(v1 * v1);

    __shared__ float red[4][6];
    int wp = t >> 5, ln = t & 31;
    if (ln == 0) { red[0][wp] = s0; red[1][wp] = q0; red[2][wp] = s1; red[3][wp] = q1; }
    __syncthreads();

    float S0 = 0, Q0 = 0, S1 = 0, Q1 = 0;
#pragma unroll
    for (int i = 0; i < 6; i++) { S0 += red[0][i]; Q0 += red[1][i]; S1 += red[2][i]; Q1 += red[3][i]; }

    const float inv = 1.0f / (float)CDIM;
    float m0 = S0 * inv, m1 = S1 * inv;
    float r0 = rsqrtf(Q0 * inv - m0 * m0 + 1e-5f);
    float r1 = rsqrtf(Q1 * inv - m1 * m1 + 1e-5f);

    float gg = g[t], bv = bb[t];
    xw [(size_t)r * CDIM + t] = (v0 - m0) * r0 * gg + bv;
    x1w[(size_t)r * CDIM + t] = (v1 - m1) * r1 * gg + bv;
}

// ---------------------------------------------------------------------------
// Kernel: plain LayerNorm (no gather), 192 thr / token
// ---------------------------------------------------------------------------
__global__ void ln2_kernel(const float* __restrict__ x,
                           const float* __restrict__ g,
                           const float* __restrict__ bb,
                           float* __restrict__ out)
{
    int r = blockIdx.x;
    int t = threadIdx.x;

    float v = x[(size_t)r * CDIM + t];
    float s = warp_sum(v), q = warp_sum(v * v);

    __shared__ float red[2][6];
    int wp = t >> 5, ln = t & 31;
    if (ln == 0) { red[0][wp] = s; red[1][wp] = q; }
    __syncthreads();

    float S = 0, Q = 0;
#pragma unroll
    for (int i = 0; i < 6; i++) { S += red[0][i]; Q += red[1][i]; }

    const float inv = 1.0f / (float)CDIM;
    float m  = S * inv;
    float rs = rsqrtf(Q * inv - m * m + 1e-5f);
    out[(size_t)r * CDIM + t] = (v - m) * rs * g[t] + bb[t];
}

// ---------------------------------------------------------------------------
// Tiled fp32 SGEMM  C[M,N] = A[M,K] @ B[K,N] (+ epilogue)
// BM=128, BN=64, BK=16, 256 threads, 8x4 microtile. All dims divide evenly.
// EPI: 0 = bias, 1 = bias+gelu, 2 = bias + scatter(window->image) + residual,
//      3 = bias + residual
// ---------------------------------------------------------------------------
#define BM 128
#define BN 64
#define BK 16

template <int EPI>
__global__ __launch_bounds__(256)
void gemm_kernel(const float* __restrict__ A, const float* __restrict__ B,
                 const float* __restrict__ bias, const float* __restrict__ res,
                 float* __restrict__ C, int M, int N, int K)
{
    __shared__ float As[BK][BM + 1];
    __shared__ float Bs[BK][BN];

    int tid = threadIdx.x;
    int m0  = blockIdx.x * BM;
    int n0  = blockIdx.y * BN;
    int tx  = tid & 15;     // N direction (16 * 4 = 64)
    int ty  = tid >> 4;     // M direction (16 * 8 = 128)

    float acc[8][4];
#pragma unroll
    for (int i = 0; i < 8; i++)
#pragma unroll
        for (int j = 0; j < 4; j++) acc[i][j] = 0.0f;

    for (int k0 = 0; k0 < K; k0 += BK) {
        // Load A tile (128x16), store transposed for broadcast-friendly reads
#pragma unroll
        for (int l = 0; l < 8; l++) {
            int idx = tid + l * 256;
            int rr  = idx >> 4;
            int cc  = idx & 15;
            As[cc][rr] = A[(size_t)(m0 + rr) * K + k0 + cc];
        }
        // Load B tile (16x64)
#pragma unroll
        for (int l = 0; l < 4; l++) {
            int idx = tid + l * 256;
            int rr  = idx >> 6;
            int cc  = idx & 63;
            Bs[rr][cc] = B[(size_t)(k0 + rr) * N + n0 + cc];
        }
        __syncthreads();

#pragma unroll
        for (int kk = 0; kk < BK; kk++) {
            float a[8], b[4];
#pragma unroll
            for (int i = 0; i < 8; i++) a[i] = As[kk][ty * 8 + i];
#pragma unroll
            for (int j = 0; j < 4; j++) b[j] = Bs[kk][tx * 4 + j];
#pragma unroll
            for (int i = 0; i < 8; i++)
#pragma unroll
                for (int j = 0; j < 4; j++)
                    acc[i][j] = fmaf(a[i], b[j], acc[i][j]);
        }
        __syncthreads();
    }

#pragma unroll
    for (int i = 0; i < 8; i++) {
        int row  = m0 + ty * 8 + i;
        int orow = (EPI == 2) ? win_src_row(row) : row;
#pragma unroll
        for (int j = 0; j < 4; j++) {
            int col = n0 + tx * 4 + j;
            float v = acc[i][j] + bias[col];
            if (EPI == 1) v = gelu_exact(v);
            if (EPI == 2 || EPI == 3) v += res[(size_t)orow * N + col];
            C[(size_t)orow * N + col] = v;
        }
    }
}

// ---------------------------------------------------------------------------
// Attention: one block per (window, head), 64 threads, each owns a query row.
// ---------------------------------------------------------------------------
__global__ __launch_bounds__(64)
void attn_kernel(const float* __restrict__ q,
                 const float* __restrict__ kv,
                 const float* __restrict__ rpb,      // [225,6]
                 const float* __restrict__ mask,     // [512,64,64]
                 float* __restrict__ out)
{
    __shared__ float Ks[64][32];
    __shared__ float Vs[64][32];
    __shared__ float Ss[64][65];
    __shared__ float Rp[225 * 6];

    int win  = blockIdx.x;
    int head = blockIdx.y;
    int t    = threadIdx.x;

    // stage K, V for this (window, head)
    const size_t kvbase = (size_t)win * 64 * (2 * CDIM) + head * HDIM;
    for (int idx = t; idx < 64 * 32; idx += 64) {
        int m = idx >> 5, d = idx & 31;
        Ks[m][d] = kv[kvbase + (size_t)m * (2 * CDIM) + d];
        Vs[m][d] = kv[kvbase + (size_t)m * (2 * CDIM) + CDIM + d];
    }
    for (int idx = t; idx < 225 * 6; idx += 64) Rp[idx] = rpb[idx];

    const float scale = 0.17677669529663688f;  // 1/sqrt(32)
    float qr[32];
    const float* qrow = q + (size_t)(win * 64 + t) * CDIM + head * HDIM;
#pragma unroll
    for (int d = 0; d < 32; d++) qr[d] = qrow[d] * scale;

    __syncthreads();

    int i1 = t >> 3, j1 = t & 7;
    const float* mrow = mask + (size_t)(win & (NW - 1)) * (64 * 64) + t * 64;

    float mx = -1e30f;
    for (int m = 0; m < 64; m++) {
        float s = 0.0f;
#pragma unroll
        for (int d = 0; d < 32; d++) s = fmaf(qr[d], Ks[m][d], s);
        int i2 = m >> 3, j2 = m & 7;
        int ridx = (i1 - i2 + 7) * 15 + (j1 - j2 + 7);
        s += Rp[ridx * 6 + head] + mrow[m];
        Ss[t][m] = s;
        mx = fmaxf(mx, s);
    }

    float sum = 0.0f;
    for (int m = 0; m < 64; m++) {
        float e = __expf(Ss[t][m] - mx);
        Ss[t][m] = e;
        sum += e;
    }
    float invs = 1.0f / sum;

    float od[32];
#pragma unroll
    for (int d = 0; d < 32; d++) od[d] = 0.0f;
    for (int m = 0; m < 64; m++) {
        float w = Ss[t][m];
#pragma unroll
        for (int d = 0; d < 32; d++) od[d] = fmaf(w, Vs[m][d], od[d]);
    }

    float* orow = out + (size_t)(win * 64 + t) * CDIM + head * HDIM;
#pragma unroll
    for (int d = 0; d < 32; d++) orow[d] = od[d] * invs;
}

// ---------------------------------------------------------------------------
// Launch
// ---------------------------------------------------------------------------
extern "C" void kernel_launch(void* const* d_in, const int* in_sizes, int n_in,
                              void* d_out, int out_size)
{
    const float* x       = (const float*)d_in[0];
    const float* x1      = (const float*)d_in[1];
    const float* mask    = (const float*)d_in[2];
    const float* norm1_g = (const float*)d_in[3];
    const float* norm1_b = (const float*)d_in[4];
    const float* q_w     = (const float*)d_in[5];
    const float* q_b     = (const float*)d_in[6];
    const float* kv_w    = (const float*)d_in[7];
    const float* kv_b    = (const float*)d_in[8];
    const float* rpb     = (const float*)d_in[9];
    const float* proj_w  = (const float*)d_in[10];
    const float* proj_b  = (const float*)d_in[11];
    const float* norm2_g = (const float*)d_in[12];
    const float* norm2_b = (const float*)d_in[13];
    const float* fc1_w   = (const float*)d_in[14];
    const float* fc1_b   = (const float*)d_in[15];
    const float* fc2_w   = (const float*)d_in[16];
    const float* fc2_b   = (const float*)d_in[17];
    // d_in[18], d_in[19]: H, W scalars (compile-time constants here)

    float *xw, *x1w, *qb, *kvb, *ao, *xo, *xn2, *hb;
    cudaGetSymbolAddress((void**)&xw,  g_xw);
    cudaGetSymbolAddress((void**)&x1w, g_x1w);
    cudaGetSymbolAddress((void**)&qb,  g_q);
    cudaGetSymbolAddress((void**)&kvb, g_kv);
    cudaGetSymbolAddress((void**)&ao,  g_ao);
    cudaGetSymbolAddress((void**)&xo,  g_xo);
    cudaGetSymbolAddress((void**)&xn2, g_xn2);
    cudaGetSymbolAddress((void**)&hb,  g_h);

    float* out = (float*)d_out;

    // 1) LN1 + gather into window layout
    ln1_gather_kernel<<<MROWS, CDIM>>>(x, x1, norm1_g, norm1_b, xw, x1w);

    // 2) q = x1w @ q_w + q_b       [131072,192] @ [192,192]
    gemm_kernel<0><<<dim3(MROWS / BM, CDIM / BN), 256>>>(x1w, q_w, q_b, nullptr, qb,
                                                         MROWS, CDIM, CDIM);
    // 3) kv = xw @ kv_w + kv_b     [131072,192] @ [192,384]
    gemm_kernel<0><<<dim3(MROWS / BM, (2 * CDIM) / BN), 256>>>(xw, kv_w, kv_b, nullptr, kvb,
                                                               MROWS, 2 * CDIM, CDIM);
    // 4) attention per (window, head)
    attn_kernel<<<dim3(BWIN, HEADS), 64>>>(qb, kvb, rpb, mask, ao);

    // 5) proj + window-reverse scatter + residual(x)  -> xo (image layout)
    gemm_kernel<2><<<dim3(MROWS / BM, CDIM / BN), 256>>>(ao, proj_w, proj_b, x, xo,
                                                         MROWS, CDIM, CDIM);
    // 6) LN2
    ln2_kernel<<<MROWS, CDIM>>>(xo, norm2_g, norm2_b, xn2);

    // 7) h = gelu(xn2 @ fc1_w + fc1_b)   [131072,192] @ [192,768]
    gemm_kernel<1><<<dim3(MROWS / BM, HIDDEN / BN), 256>>>(xn2, fc1_w, fc1_b, nullptr, hb,
                                                           MROWS, HIDDEN, CDIM);
    // 8) out = xo + h @ fc2_w + fc2_b    [131072,768] @ [768,192]
    gemm_kernel<3><<<dim3(MROWS / BM, CDIM / BN), 256>>>(hb, fc2_w, fc2_b, xo, out,
                                                         MROWS, CDIM, HIDDEN);
}